// round 1
// baseline (speedup 1.0000x reference)
#include <cuda_runtime.h>
#include <math.h>

#define NN   50000
#define EE   640000
#define ETOT (EE + NN)
#define DD   128

// ---------------- scratch (device globals; no allocation allowed) ----------
__device__ __align__(16) float g_CAT[(size_t)NN * 256];
__device__ __align__(16) float g_X  [(size_t)NN * DD];
__device__ __align__(16) float g_XP [(size_t)NN * DD];
__device__ __align__(16) float g_AGG[(size_t)NN * DD];
__device__ __align__(16) float g_GI [(size_t)NN * 3 * DD];
__device__ __align__(16) float g_GH [(size_t)NN * 3 * DD];
__device__ float g_ASRC[NN];
__device__ float g_ADST[NN];
__device__ float g_BN[256];
__device__ int   g_deg[NN];
__device__ int   g_off[NN + 1];
__device__ int   g_cur[NN];
__device__ int   g_csr[ETOT];

// ---------------- f32x2 helpers (2x fp32 FMA throughput on sm_103a) --------
__device__ __forceinline__ unsigned long long splat2(float x) {
    unsigned long long r;
    asm("mov.b64 %0, {%1, %1};" : "=l"(r) : "f"(x));
    return r;
}
__device__ __forceinline__ void fma2(unsigned long long& d,
                                     unsigned long long a,
                                     unsigned long long b) {
    asm("fma.rn.f32x2 %0, %1, %2, %0;" : "+l"(d) : "l"(a), "l"(b));
}

// ---------------- SGEMM: C[n,M] = A[n,K] @ W[K,M] (+bias) ------------------
// 128x128 tile per 256-thread block, 8x8 micro-tile per thread, f32x2 packed.
__global__ __launch_bounds__(256) void sgemm(
    const float* __restrict__ A, const float* __restrict__ W,
    const float* __restrict__ bias, float* __restrict__ C,
    int nrows, int K, int M)
{
    __shared__ __align__(16) float As[8][128];   // transposed A tile
    __shared__ __align__(16) float Ws[8][128];

    const int tid  = threadIdx.x;
    const int row0 = blockIdx.y * 128;
    const int col0 = blockIdx.x * 128;
    const int ty = tid >> 4;          // 0..15
    const int tx = tid & 15;          // 0..15

    unsigned long long acc[8][4];
#pragma unroll
    for (int i = 0; i < 8; i++)
#pragma unroll
        for (int j = 0; j < 4; j++) acc[i][j] = 0ULL;

    const int arow = tid >> 1;            // 0..127
    const int acol = (tid & 1) * 4;       // 0 or 4
    const int wrow = tid >> 5;            // 0..7
    const int wcol = (tid & 31) * 4;      // 0..124
    const bool aok = (row0 + arow) < nrows;
    const float* Arow = A + (size_t)(row0 + arow) * K;

    for (int k0 = 0; k0 < K; k0 += 8) {
        float4 av = make_float4(0.f, 0.f, 0.f, 0.f);
        if (aok) av = *(const float4*)(Arow + k0 + acol);
        const float4 wv = *(const float4*)(W + (size_t)(k0 + wrow) * M + col0 + wcol);

        __syncthreads();
        As[acol + 0][arow] = av.x;
        As[acol + 1][arow] = av.y;
        As[acol + 2][arow] = av.z;
        As[acol + 3][arow] = av.w;
        *(float4*)&Ws[wrow][wcol] = wv;
        __syncthreads();

#pragma unroll
        for (int k = 0; k < 8; k++) {
            const float4 a0 = *(const float4*)&As[k][ty * 4];
            const float4 a1 = *(const float4*)&As[k][ty * 4 + 64];
            const ulonglong2 b0 = *(const ulonglong2*)&Ws[k][tx * 4];
            const ulonglong2 b1 = *(const ulonglong2*)&Ws[k][tx * 4 + 64];
            unsigned long long sa[8];
            sa[0] = splat2(a0.x); sa[1] = splat2(a0.y);
            sa[2] = splat2(a0.z); sa[3] = splat2(a0.w);
            sa[4] = splat2(a1.x); sa[5] = splat2(a1.y);
            sa[6] = splat2(a1.z); sa[7] = splat2(a1.w);
#pragma unroll
            for (int i = 0; i < 8; i++) {
                fma2(acc[i][0], sa[i], b0.x);
                fma2(acc[i][1], sa[i], b0.y);
                fma2(acc[i][2], sa[i], b1.x);
                fma2(acc[i][3], sa[i], b1.y);
            }
        }
    }

    const int colA = col0 + tx * 4;
    const int colB = colA + 64;
    float4 bA = make_float4(0.f, 0.f, 0.f, 0.f);
    float4 bB = bA;
    if (bias) {
        bA = *(const float4*)&bias[colA];
        bB = *(const float4*)&bias[colB];
    }
#pragma unroll
    for (int i = 0; i < 8; i++) {
        const int r = row0 + ty * 4 + ((i < 4) ? i : 64 + (i - 4));
        if (r < nrows) {
            const float2 p0 = *(const float2*)&acc[i][0];
            const float2 p1 = *(const float2*)&acc[i][1];
            const float2 p2 = *(const float2*)&acc[i][2];
            const float2 p3 = *(const float2*)&acc[i][3];
            float4 oA = make_float4(p0.x + bA.x, p0.y + bA.y, p1.x + bA.z, p1.y + bA.w);
            float4 oB = make_float4(p2.x + bB.x, p2.y + bB.y, p3.x + bB.z, p3.y + bB.w);
            *(float4*)&C[(size_t)r * M + colA] = oA;
            *(float4*)&C[(size_t)r * M + colB] = oB;
        }
    }
}

// ---------------- graph / CSR build ----------------------------------------
__global__ void k_zero_int(int* p, int n) {
    int i = blockIdx.x * blockDim.x + threadIdx.x;
    if (i < n) p[i] = 0;
}
__global__ void k_zero_f(float* p, int n) {
    int i = blockIdx.x * blockDim.x + threadIdx.x;
    if (i < n) p[i] = 0.f;
}
__global__ void k_deg_count(const int* __restrict__ ei) {
    int i = blockIdx.x * blockDim.x + threadIdx.x;
    if (i < ETOT) {
        int d = (i < EE) ? ei[EE + i] : (i - EE);
        atomicAdd(&g_deg[d], 1);
    }
}
__global__ void k_scan() {  // 1 block, 1024 threads: exclusive scan of g_deg
    __shared__ int sh[1024];
    __shared__ int carry;
    const int tid = threadIdx.x;
    if (tid == 0) carry = 0;
    __syncthreads();
    for (int base = 0; base < NN; base += 1024) {
        const int v = base + tid;
        const int x = (v < NN) ? g_deg[v] : 0;
        sh[tid] = x;
        __syncthreads();
        for (int o = 1; o < 1024; o <<= 1) {
            int t = (tid >= o) ? sh[tid - o] : 0;
            __syncthreads();
            sh[tid] += t;
            __syncthreads();
        }
        const int excl = carry + sh[tid] - x;
        if (v < NN) { g_off[v] = excl; g_cur[v] = excl; }
        __syncthreads();
        if (tid == 0) carry += sh[1023];
        __syncthreads();
    }
    if (tid == 0) g_off[NN] = carry;
}
__global__ void k_csr_scatter(const int* __restrict__ ei) {
    int i = blockIdx.x * blockDim.x + threadIdx.x;
    if (i < ETOT) {
        int s, d;
        if (i < EE) { s = ei[i]; d = ei[EE + i]; }
        else        { s = i - EE; d = i - EE; }
        int slot = atomicAdd(&g_cur[d], 1);
        g_csr[slot] = s;
    }
}

// ---------------- time encode + concat -------------------------------------
__global__ void k_cat(const float* __restrict__ nf, const float* __restrict__ ts,
                      const float* __restrict__ freq, const float* __restrict__ phase)
{
    int idx = blockIdx.x * blockDim.x + threadIdx.x;
    if (idx < NN * DD) {
        int n = idx / DD, j = idx % DD;
        g_CAT[(size_t)n * 256 + j] = nf[idx];
        g_CAT[(size_t)n * 256 + DD + j] = cosf(ts[n] * freq[j] + phase[j]);
    }
}

// ---------------- attention scores: row dots with a_src / a_dst ------------
__global__ void k_attn(const float* __restrict__ XP,
                       const float* __restrict__ av_s, const float* __restrict__ av_d)
{
    int v = (blockIdx.x * blockDim.x + threadIdx.x) >> 5;
    int lane = threadIdx.x & 31;
    if (v >= NN) return;
    const float4 x = *(const float4*)&XP[(size_t)v * DD + lane * 4];
    const float4 a = *(const float4*)&av_s[lane * 4];
    const float4 d = *(const float4*)&av_d[lane * 4];
    float s = x.x * a.x + x.y * a.y + x.z * a.z + x.w * a.w;
    float t = x.x * d.x + x.y * d.y + x.z * d.z + x.w * d.w;
#pragma unroll
    for (int o = 16; o; o >>= 1) {
        s += __shfl_xor_sync(0xffffffffu, s, o);
        t += __shfl_xor_sync(0xffffffffu, t, o);
    }
    if (lane == 0) { g_ASRC[v] = s; g_ADST[v] = t; }
}

// ---------------- GAT aggregation: warp per dst node (CSR) -----------------
__global__ void k_gat_agg(const float* __restrict__ XP,
                          const float* __restrict__ bias,
                          float* __restrict__ out)
{
    int v = (blockIdx.x * blockDim.x + threadIdx.x) >> 5;
    int lane = threadIdx.x & 31;
    if (v >= NN) return;
    const int beg = g_off[v], end = g_off[v + 1];
    const float adv = g_ADST[v];

    // pass 1: segment max of leaky_relu(e)
    float m = -1e30f;
    for (int i = beg + lane; i < end; i += 32) {
        float e = g_ASRC[g_csr[i]] + adv;
        e = (e > 0.f) ? e : 0.2f * e;
        m = fmaxf(m, e);
    }
#pragma unroll
    for (int o = 16; o; o >>= 1) m = fmaxf(m, __shfl_xor_sync(0xffffffffu, m, o));

    // pass 2: exp-sum + weighted feature accumulation
    float ssum = 0.f;
    float4 acc = make_float4(0.f, 0.f, 0.f, 0.f);
    for (int i = beg; i < end; i++) {
        const int s = g_csr[i];
        float e = g_ASRC[s] + adv;
        e = (e > 0.f) ? e : 0.2f * e;
        const float w = expf(e - m);
        ssum += w;
        const float4 xv = *(const float4*)&XP[(size_t)s * DD + lane * 4];
        acc.x += w * xv.x; acc.y += w * xv.y;
        acc.z += w * xv.z; acc.w += w * xv.w;
    }
    const float inv = 1.f / (ssum + 1e-16f);
    const float4 b4 = *(const float4*)&bias[lane * 4];
    float4 o4 = make_float4(acc.x * inv + b4.x, acc.y * inv + b4.y,
                            acc.z * inv + b4.z, acc.w * inv + b4.w);
    *(float4*)&out[(size_t)v * DD + lane * 4] = o4;
}

// ---------------- GRU gates (+optional relu, +optional skip add) -----------
__global__ void k_gru(const float* __restrict__ GI, const float* __restrict__ GH,
                      const float* __restrict__ h, const float* __restrict__ skip,
                      float* __restrict__ out, int do_relu)
{
    int idx = blockIdx.x * blockDim.x + threadIdx.x;
    if (idx >= NN * DD) return;
    int n = idx / DD, j = idx % DD;
    size_t base = (size_t)n * 3 * DD;
    float ir = GI[base + j],       hr = GH[base + j];
    float iz = GI[base + DD + j],  hz = GH[base + DD + j];
    float in_ = GI[base + 2 * DD + j], hn = GH[base + 2 * DD + j];
    float r = 1.f / (1.f + expf(-(ir + hr)));
    float z = 1.f / (1.f + expf(-(iz + hz)));
    float nn = tanhf(in_ + r * hn);
    float hv = h[idx];
    float o = (1.f - z) * nn + z * hv;
    if (skip) o += skip[idx];
    if (do_relu) o = fmaxf(o, 0.f);
    out[idx] = o;
}

// ---------------- BatchNorm over rows ---------------------------------------
__global__ void k_bn_reduce(const float* __restrict__ H2) {
    int c = threadIdx.x;                     // 0..127
    int r0 = blockIdx.x * 128;
    int rend = min(r0 + 128, NN);
    float s = 0.f, s2 = 0.f;
    for (int r = r0; r < rend; r++) {
        float v = H2[(size_t)r * DD + c];
        s += v; s2 += v * v;
    }
    atomicAdd(&g_BN[c], s);
    atomicAdd(&g_BN[128 + c], s2);
}
__global__ void k_bn_norm(float* __restrict__ H2) {
    int idx = blockIdx.x * blockDim.x + threadIdx.x;
    if (idx >= NN * DD) return;
    int j = idx % DD;
    float mu = g_BN[j] * (1.f / NN);
    float var = g_BN[128 + j] * (1.f / NN) - mu * mu;
    H2[idx] = (H2[idx] - mu) * rsqrtf(var + 1e-5f);
}

// ---------------- launch ----------------------------------------------------
extern "C" void kernel_launch(void* const* d_in, const int* in_sizes, int n_in,
                              void* d_out, int out_size)
{
    const float* nf       = (const float*)d_in[0];
    const int*   ei       = (const int*)  d_in[1];
    const float* x_prev1  = (const float*)d_in[2];
    const float* x_prev2  = (const float*)d_in[3];
    const float* ts       = (const float*)d_in[4];
    const float* freq     = (const float*)d_in[5];
    const float* phase    = (const float*)d_in[6];
    const float* merge_W  = (const float*)d_in[7];
    const float* merge_b  = (const float*)d_in[8];
    const float* gat1_W   = (const float*)d_in[9];
    const float* gat1_as  = (const float*)d_in[10];
    const float* gat1_ad  = (const float*)d_in[11];
    const float* gat1_b   = (const float*)d_in[12];
    const float* gru1_Wih = (const float*)d_in[13];
    const float* gru1_Whh = (const float*)d_in[14];
    const float* gru1_bih = (const float*)d_in[15];
    const float* gru1_bhh = (const float*)d_in[16];
    const float* gat2_W   = (const float*)d_in[17];
    const float* gat2_as  = (const float*)d_in[18];
    const float* gat2_ad  = (const float*)d_in[19];
    const float* gat2_b   = (const float*)d_in[20];
    const float* gru2_Wih = (const float*)d_in[21];
    const float* gru2_Whh = (const float*)d_in[22];
    const float* gru2_bih = (const float*)d_in[23];
    const float* gru2_bhh = (const float*)d_in[24];
    const float* skip_W   = (const float*)d_in[25];
    const float* skip_b   = (const float*)d_in[26];

    float* H1 = (float*)d_out;
    float* H2 = H1 + (size_t)NN * DD;

    float *pCAT, *pX, *pXP, *pAGG, *pGI, *pGH, *pBN;
    int *pDeg;
    cudaGetSymbolAddress((void**)&pCAT, g_CAT);
    cudaGetSymbolAddress((void**)&pX,   g_X);
    cudaGetSymbolAddress((void**)&pXP,  g_XP);
    cudaGetSymbolAddress((void**)&pAGG, g_AGG);
    cudaGetSymbolAddress((void**)&pGI,  g_GI);
    cudaGetSymbolAddress((void**)&pGH,  g_GH);
    cudaGetSymbolAddress((void**)&pBN,  g_BN);
    cudaGetSymbolAddress((void**)&pDeg, g_deg);

    const int TB = 256;
    const int gb_nodes = (NN + TB - 1) / TB;
    const int gb_edges = (ETOT + TB - 1) / TB;
    const int gb_nd    = (NN * DD + TB - 1) / TB;
    const int gb_warp  = (NN * 32 + TB - 1) / TB;   // 1 warp per node
    const dim3 gemm_blk(256);
    const int rtiles = (NN + 127) / 128;

    // CSR build (shared by both GAT layers)
    k_zero_int<<<gb_nodes, TB>>>(pDeg, NN);
    k_deg_count<<<gb_edges, TB>>>(ei);
    k_scan<<<1, 1024>>>();
    k_csr_scatter<<<gb_edges, TB>>>(ei);

    // time-encode + merge
    k_cat<<<gb_nd, TB>>>(nf, ts, freq, phase);
    sgemm<<<dim3(1, rtiles), gemm_blk>>>(pCAT, merge_W, merge_b, pX, NN, 256, DD);

    // layer 1: GAT
    sgemm<<<dim3(1, rtiles), gemm_blk>>>(pX, gat1_W, nullptr, pXP, NN, DD, DD);
    k_attn<<<gb_warp, TB>>>(pXP, gat1_as, gat1_ad);
    k_gat_agg<<<gb_warp, TB>>>(pXP, gat1_b, pAGG);
    // layer 1: GRU (+relu) -> H1
    sgemm<<<dim3(3, rtiles), gemm_blk>>>(pAGG, gru1_Wih, gru1_bih, pGI, NN, DD, 3 * DD);
    sgemm<<<dim3(3, rtiles), gemm_blk>>>(x_prev1, gru1_Whh, gru1_bhh, pGH, NN, DD, 3 * DD);
    k_gru<<<gb_nd, TB>>>(pGI, pGH, x_prev1, nullptr, H1, 1);

    // layer 2: GAT on H1
    sgemm<<<dim3(1, rtiles), gemm_blk>>>(H1, gat2_W, nullptr, pXP, NN, DD, DD);
    k_attn<<<gb_warp, TB>>>(pXP, gat2_as, gat2_ad);
    k_gat_agg<<<gb_warp, TB>>>(pXP, gat2_b, pAGG);
    // layer 2: GRU + skip -> H2 (pre-BN)
    sgemm<<<dim3(3, rtiles), gemm_blk>>>(pAGG, gru2_Wih, gru2_bih, pGI, NN, DD, 3 * DD);
    sgemm<<<dim3(3, rtiles), gemm_blk>>>(x_prev2, gru2_Whh, gru2_bhh, pGH, NN, DD, 3 * DD);
    sgemm<<<dim3(1, rtiles), gemm_blk>>>(pX, skip_W, skip_b, pXP, NN, DD, DD); // skip into XP
    k_gru<<<gb_nd, TB>>>(pGI, pGH, x_prev2, pXP, H2, 0);

    // BatchNorm (training stats, identity affine)
    k_zero_f<<<1, 256>>>(pBN, 256);
    k_bn_reduce<<<rtiles, 128>>>(H2);
    k_bn_norm<<<gb_nd, TB>>>(H2);
}

// round 5
// speedup vs baseline: 1.1909x; 1.1909x over previous
#include <cuda_runtime.h>
#include <cuda_bf16.h>
#include <stdint.h>
#include <math.h>

#define NN   50000
#define EE   640000
#define ETOT (EE + NN)
#define DD   128

// ---------------- scratch (device globals; no allocation allowed) ----------
__device__ __align__(16) float g_CAT[(size_t)NN * 256];
__device__ __align__(16) float g_X  [(size_t)NN * DD];
__device__ __align__(16) float g_XP [(size_t)NN * DD];
__device__ __align__(16) float g_AGG[(size_t)NN * DD];
__device__ __align__(16) float g_GI [(size_t)NN * 3 * DD];
__device__ __align__(16) float g_GH [(size_t)NN * 3 * DD];
__device__ float g_ASRC[NN];
__device__ float g_ADST[NN];
__device__ float g_BN[256];
__device__ int   g_deg[NN];
__device__ int   g_off[NN + 1];
__device__ int   g_cur[NN];
__device__ int   g_csr[ETOT];

// ---------------- mma.sync bf16 split GEMM ---------------------------------
// Block: 256 threads, 128x128 output tile. Warp grid 4x2 (rows x cols),
// warp tile 32x64 via m16n8k16. fp32 inputs split into hi/lo bf16;
// C += Ah*Bh + Ah*Bl + Al*Bh (lo*lo dropped, ~2^-16 relative).
#define KC     32          // k-chunk per smem stage
#define SPAD   40          // smem row stride in bf16 elems (32 + 8 pad)

__device__ __forceinline__ void mma_bf16(float c[4], const uint32_t a[4],
                                         uint32_t b0, uint32_t b1) {
    asm volatile(
        "mma.sync.aligned.m16n8k16.row.col.f32.bf16.bf16.f32 "
        "{%0,%1,%2,%3}, {%4,%5,%6,%7}, {%8,%9}, {%0,%1,%2,%3};"
        : "+f"(c[0]), "+f"(c[1]), "+f"(c[2]), "+f"(c[3])
        : "r"(a[0]), "r"(a[1]), "r"(a[2]), "r"(a[3]), "r"(b0), "r"(b1));
}

__device__ __forceinline__ void split2(float x0, float x1,
                                       uint32_t& hi, uint32_t& lo) {
    __nv_bfloat162 h = __floats2bfloat162_rn(x0, x1);
    float r0 = x0 - __bfloat162float(h.x);
    float r1 = x1 - __bfloat162float(h.y);
    __nv_bfloat162 l = __floats2bfloat162_rn(r0, r1);
    hi = *reinterpret_cast<uint32_t*>(&h);
    lo = *reinterpret_cast<uint32_t*>(&l);
}

__global__ __launch_bounds__(256) void gemm_mma(
    const float* __restrict__ A, const float* __restrict__ W,
    const float* __restrict__ bias, float* __restrict__ C,
    int nrows, int K, int M,
    const float* __restrict__ attn_s, const float* __restrict__ attn_d,
    float* __restrict__ out_s, float* __restrict__ out_d)
{
    __shared__ __nv_bfloat16 Ah[128 * SPAD], Al[128 * SPAD];
    __shared__ __nv_bfloat16 Bh[128 * SPAD], Bl[128 * SPAD];
    __shared__ float red_s[2][128], red_d[2][128];

    const int tid = threadIdx.x;
    const int wid = tid >> 5, lane = tid & 31;
    const int g = lane >> 2, tg = lane & 3;
    const int wr = (wid & 3) * 32;         // warp row offset in tile
    const int wc = (wid >> 2) * 64;        // warp col offset in tile
    const int row0 = blockIdx.y * 128;
    const int col0 = blockIdx.x * 128;

    float c[2][8][4];
#pragma unroll
    for (int mt = 0; mt < 2; mt++)
#pragma unroll
        for (int nt = 0; nt < 8; nt++)
#pragma unroll
            for (int j = 0; j < 4; j++) c[mt][nt][j] = 0.f;

    for (int k0 = 0; k0 < K; k0 += KC) {
        // ---- stage A chunk: 128 rows x 32 k (float4 coalesced) ----
#pragma unroll
        for (int i = 0; i < 4; i++) {
            const int slot = i * 256 + tid;        // 1024 slots = 128r x 8 quads
            const int r = slot >> 3;
            const int kq = (slot & 7) * 4;
            float4 a4 = make_float4(0.f, 0.f, 0.f, 0.f);
            if (row0 + r < nrows)
                a4 = *(const float4*)(A + (size_t)(row0 + r) * K + k0 + kq);
            uint32_t h0, l0, h1, l1;
            split2(a4.x, a4.y, h0, l0);
            split2(a4.z, a4.w, h1, l1);
            const int base = r * SPAD + kq;
            *(uint32_t*)&Ah[base]     = h0;
            *(uint32_t*)&Ah[base + 2] = h1;
            *(uint32_t*)&Al[base]     = l0;
            *(uint32_t*)&Al[base + 2] = l1;
        }
        // ---- stage B chunk: Bs[n][k] = W[k0+k][col0+n], coalesced over n ----
#pragma unroll
        for (int i = 0; i < 8; i++) {
            const int slot = i * 256 + tid;        // 2048 slots = 128n x 16 kpairs
            const int n = slot & 127;
            const int k = (slot >> 7) * 2;
            const float w0 = W[(size_t)(k0 + k) * M + col0 + n];
            const float w1 = W[(size_t)(k0 + k + 1) * M + col0 + n];
            uint32_t h, l;
            split2(w0, w1, h, l);
            const int base = n * SPAD + k;
            *(uint32_t*)&Bh[base] = h;
            *(uint32_t*)&Bl[base] = l;
        }
        __syncthreads();

#pragma unroll
        for (int ks = 0; ks < KC / 16; ks++) {
            const int kk = ks * 16 + tg * 2;
            uint32_t ah[2][4], al[2][4];
#pragma unroll
            for (int mt = 0; mt < 2; mt++) {
                const int r = wr + mt * 16 + g;
                ah[mt][0] = *(const uint32_t*)&Ah[r * SPAD + kk];
                ah[mt][1] = *(const uint32_t*)&Ah[(r + 8) * SPAD + kk];
                ah[mt][2] = *(const uint32_t*)&Ah[r * SPAD + kk + 8];
                ah[mt][3] = *(const uint32_t*)&Ah[(r + 8) * SPAD + kk + 8];
                al[mt][0] = *(const uint32_t*)&Al[r * SPAD + kk];
                al[mt][1] = *(const uint32_t*)&Al[(r + 8) * SPAD + kk];
                al[mt][2] = *(const uint32_t*)&Al[r * SPAD + kk + 8];
                al[mt][3] = *(const uint32_t*)&Al[(r + 8) * SPAD + kk + 8];
            }
#pragma unroll
            for (int nt = 0; nt < 8; nt++) {
                const int n = wc + nt * 8 + g;
                const uint32_t bh0 = *(const uint32_t*)&Bh[n * SPAD + kk];
                const uint32_t bh1 = *(const uint32_t*)&Bh[n * SPAD + kk + 8];
                const uint32_t bl0 = *(const uint32_t*)&Bl[n * SPAD + kk];
                const uint32_t bl1 = *(const uint32_t*)&Bl[n * SPAD + kk + 8];
#pragma unroll
                for (int mt = 0; mt < 2; mt++) {
                    mma_bf16(c[mt][nt], ah[mt], bh0, bh1);
                    mma_bf16(c[mt][nt], ah[mt], bl0, bl1);
                    mma_bf16(c[mt][nt], al[mt], bh0, bh1);
                }
            }
        }
        __syncthreads();
    }

    // ---- epilogue: bias add, store, optional fused attention dots ----
    float ss[2][2] = {{0.f, 0.f}, {0.f, 0.f}};
    float sd[2][2] = {{0.f, 0.f}, {0.f, 0.f}};
#pragma unroll
    for (int mt = 0; mt < 2; mt++) {
#pragma unroll
        for (int nt = 0; nt < 8; nt++) {
            const int colL = wc + nt * 8 + tg * 2;    // 0..127 within tile
            const int col = col0 + colL;
            float b0 = 0.f, b1 = 0.f;
            if (bias) { b0 = bias[col]; b1 = bias[col + 1]; }
            const float v0 = c[mt][nt][0] + b0;
            const float v1 = c[mt][nt][1] + b1;
            const float v2 = c[mt][nt][2] + b0;
            const float v3 = c[mt][nt][3] + b1;
            const int rA = row0 + wr + mt * 16 + g;
            const int rB = rA + 8;
            if (rA < nrows) *(float2*)&C[(size_t)rA * M + col] = make_float2(v0, v1);
            if (rB < nrows) *(float2*)&C[(size_t)rB * M + col] = make_float2(v2, v3);
            if (out_s) {
                const float s0 = attn_s[colL], s1 = attn_s[colL + 1];
                const float d0 = attn_d[colL], d1 = attn_d[colL + 1];
                ss[mt][0] += v0 * s0 + v1 * s1;
                ss[mt][1] += v2 * s0 + v3 * s1;
                sd[mt][0] += v0 * d0 + v1 * d1;
                sd[mt][1] += v2 * d0 + v3 * d1;
            }
        }
    }
    if (out_s) {
#pragma unroll
        for (int mt = 0; mt < 2; mt++)
#pragma unroll
            for (int h = 0; h < 2; h++) {
                ss[mt][h] += __shfl_xor_sync(0xffffffffu, ss[mt][h], 1);
                ss[mt][h] += __shfl_xor_sync(0xffffffffu, ss[mt][h], 2);
                sd[mt][h] += __shfl_xor_sync(0xffffffffu, sd[mt][h], 1);
                sd[mt][h] += __shfl_xor_sync(0xffffffffu, sd[mt][h], 2);
            }
        if (tg == 0) {
            const int wcid = wid >> 2;
#pragma unroll
            for (int mt = 0; mt < 2; mt++)
#pragma unroll
                for (int h = 0; h < 2; h++) {
                    const int rl = wr + mt * 16 + h * 8 + g;
                    red_s[wcid][rl] = ss[mt][h];
                    red_d[wcid][rl] = sd[mt][h];
                }
        }
        __syncthreads();
        if (tid < 128) {
            const int r = row0 + tid;
            if (r < nrows) {
                out_s[r] = red_s[0][tid] + red_s[1][tid];
                out_d[r] = red_d[0][tid] + red_d[1][tid];
            }
        }
    }
}

// ---------------- graph / CSR build ----------------------------------------
__global__ void k_zero_int(int* p, int n) {
    int i = blockIdx.x * blockDim.x + threadIdx.x;
    if (i < n) p[i] = 0;
}
__global__ void k_zero_f(float* p, int n) {
    int i = blockIdx.x * blockDim.x + threadIdx.x;
    if (i < n) p[i] = 0.f;
}
__global__ void k_deg_count(const int* __restrict__ ei) {
    int i = blockIdx.x * blockDim.x + threadIdx.x;
    if (i < ETOT) {
        int d = (i < EE) ? ei[EE + i] : (i - EE);
        atomicAdd(&g_deg[d], 1);
    }
}
__global__ void k_scan() {  // 1 block, 1024 threads: exclusive scan of g_deg
    __shared__ int sh[1024];
    __shared__ int carry;
    const int tid = threadIdx.x;
    if (tid == 0) carry = 0;
    __syncthreads();
    for (int base = 0; base < NN; base += 1024) {
        const int v = base + tid;
        const int x = (v < NN) ? g_deg[v] : 0;
        sh[tid] = x;
        __syncthreads();
        for (int o = 1; o < 1024; o <<= 1) {
            int t = (tid >= o) ? sh[tid - o] : 0;
            __syncthreads();
            sh[tid] += t;
            __syncthreads();
        }
        const int excl = carry + sh[tid] - x;
        if (v < NN) { g_off[v] = excl; g_cur[v] = excl; }
        __syncthreads();
        if (tid == 0) carry += sh[1023];
        __syncthreads();
    }
    if (tid == 0) g_off[NN] = carry;
}
__global__ void k_csr_scatter(const int* __restrict__ ei) {
    int i = blockIdx.x * blockDim.x + threadIdx.x;
    if (i < ETOT) {
        int s, d;
        if (i < EE) { s = ei[i]; d = ei[EE + i]; }
        else        { s = i - EE; d = i - EE; }
        int slot = atomicAdd(&g_cur[d], 1);
        g_csr[slot] = s;
    }
}

// ---------------- time encode + concat -------------------------------------
__global__ void k_cat(const float* __restrict__ nf, const float* __restrict__ ts,
                      const float* __restrict__ freq, const float* __restrict__ phase)
{
    int idx = blockIdx.x * blockDim.x + threadIdx.x;
    if (idx < NN * DD) {
        int n = idx / DD, j = idx % DD;
        g_CAT[(size_t)n * 256 + j] = nf[idx];
        g_CAT[(size_t)n * 256 + DD + j] = cosf(ts[n] * freq[j] + phase[j]);
    }
}

// ---------------- GAT aggregation: warp per dst node (CSR) -----------------
__global__ void k_gat_agg(const float* __restrict__ XP,
                          const float* __restrict__ bias,
                          float* __restrict__ out)
{
    int v = (blockIdx.x * blockDim.x + threadIdx.x) >> 5;
    int lane = threadIdx.x & 31;
    if (v >= NN) return;
    const int beg = g_off[v], end = g_off[v + 1];
    const float adv = g_ADST[v];

    // pass 1: segment max of leaky_relu(e)
    float m = -1e30f;
    for (int i = beg + lane; i < end; i += 32) {
        float e = g_ASRC[g_csr[i]] + adv;
        e = (e > 0.f) ? e : 0.2f * e;
        m = fmaxf(m, e);
    }
#pragma unroll
    for (int o = 16; o; o >>= 1) m = fmaxf(m, __shfl_xor_sync(0xffffffffu, m, o));

    // pass 2: exp-sum + weighted feature accumulation
    float ssum = 0.f;
    float4 acc = make_float4(0.f, 0.f, 0.f, 0.f);
    for (int i = beg; i < end; i++) {
        const int s = g_csr[i];
        float e = g_ASRC[s] + adv;
        e = (e > 0.f) ? e : 0.2f * e;
        const float w = expf(e - m);
        ssum += w;
        const float4 xv = *(const float4*)&XP[(size_t)s * DD + lane * 4];
        acc.x += w * xv.x; acc.y += w * xv.y;
        acc.z += w * xv.z; acc.w += w * xv.w;
    }
    const float inv = 1.f / (ssum + 1e-16f);
    const float4 b4 = *(const float4*)&bias[lane * 4];
    float4 o4 = make_float4(acc.x * inv + b4.x, acc.y * inv + b4.y,
                            acc.z * inv + b4.z, acc.w * inv + b4.w);
    *(float4*)&out[(size_t)v * DD + lane * 4] = o4;
}

// ---------------- GRU gates (+optional relu, +optional skip add) -----------
__global__ void k_gru(const float* __restrict__ GI, const float* __restrict__ GH,
                      const float* __restrict__ h, const float* __restrict__ skip,
                      float* __restrict__ out, int do_relu)
{
    int idx = blockIdx.x * blockDim.x + threadIdx.x;
    if (idx >= NN * DD) return;
    int n = idx / DD, j = idx % DD;
    size_t base = (size_t)n * 3 * DD;
    float ir = GI[base + j],       hr = GH[base + j];
    float iz = GI[base + DD + j],  hz = GH[base + DD + j];
    float in_ = GI[base + 2 * DD + j], hn = GH[base + 2 * DD + j];
    float r = 1.f / (1.f + expf(-(ir + hr)));
    float z = 1.f / (1.f + expf(-(iz + hz)));
    float nn = tanhf(in_ + r * hn);
    float hv = h[idx];
    float o = (1.f - z) * nn + z * hv;
    if (skip) o += skip[idx];
    if (do_relu) o = fmaxf(o, 0.f);
    out[idx] = o;
}

// ---------------- BatchNorm over rows ---------------------------------------
__global__ void k_bn_reduce(const float* __restrict__ H2) {
    int c = threadIdx.x;                     // 0..127
    int r0 = blockIdx.x * 128;
    int rend = min(r0 + 128, NN);
    float s = 0.f, s2 = 0.f;
    for (int r = r0; r < rend; r++) {
        float v = H2[(size_t)r * DD + c];
        s += v; s2 += v * v;
    }
    atomicAdd(&g_BN[c], s);
    atomicAdd(&g_BN[128 + c], s2);
}
__global__ void k_bn_norm(float* __restrict__ H2) {
    int idx = blockIdx.x * blockDim.x + threadIdx.x;
    if (idx >= NN * DD) return;
    int j = idx % DD;
    float mu = g_BN[j] * (1.f / NN);
    float var = g_BN[128 + j] * (1.f / NN) - mu * mu;
    H2[idx] = (H2[idx] - mu) * rsqrtf(var + 1e-5f);
}

// ---------------- launch ----------------------------------------------------
extern "C" void kernel_launch(void* const* d_in, const int* in_sizes, int n_in,
                              void* d_out, int out_size)
{
    const float* nf       = (const float*)d_in[0];
    const int*   ei       = (const int*)  d_in[1];
    const float* x_prev1  = (const float*)d_in[2];
    const float* x_prev2  = (const float*)d_in[3];
    const float* ts       = (const float*)d_in[4];
    const float* freq     = (const float*)d_in[5];
    const float* phase    = (const float*)d_in[6];
    const float* merge_W  = (const float*)d_in[7];
    const float* merge_b  = (const float*)d_in[8];
    const float* gat1_W   = (const float*)d_in[9];
    const float* gat1_as  = (const float*)d_in[10];
    const float* gat1_ad  = (const float*)d_in[11];
    const float* gat1_b   = (const float*)d_in[12];
    const float* gru1_Wih = (const float*)d_in[13];
    const float* gru1_Whh = (const float*)d_in[14];
    const float* gru1_bih = (const float*)d_in[15];
    const float* gru1_bhh = (const float*)d_in[16];
    const float* gat2_W   = (const float*)d_in[17];
    const float* gat2_as  = (const float*)d_in[18];
    const float* gat2_ad  = (const float*)d_in[19];
    const float* gat2_b   = (const float*)d_in[20];
    const float* gru2_Wih = (const float*)d_in[21];
    const float* gru2_Whh = (const float*)d_in[22];
    const float* gru2_bih = (const float*)d_in[23];
    const float* gru2_bhh = (const float*)d_in[24];
    const float* skip_W   = (const float*)d_in[25];
    const float* skip_b   = (const float*)d_in[26];

    float* H1 = (float*)d_out;
    float* H2 = H1 + (size_t)NN * DD;

    float *pCAT, *pX, *pXP, *pAGG, *pGI, *pGH, *pBN, *pAS, *pAD;
    int *pDeg;
    cudaGetSymbolAddress((void**)&pCAT, g_CAT);
    cudaGetSymbolAddress((void**)&pX,   g_X);
    cudaGetSymbolAddress((void**)&pXP,  g_XP);
    cudaGetSymbolAddress((void**)&pAGG, g_AGG);
    cudaGetSymbolAddress((void**)&pGI,  g_GI);
    cudaGetSymbolAddress((void**)&pGH,  g_GH);
    cudaGetSymbolAddress((void**)&pBN,  g_BN);
    cudaGetSymbolAddress((void**)&pAS,  g_ASRC);
    cudaGetSymbolAddress((void**)&pAD,  g_ADST);
    cudaGetSymbolAddress((void**)&pDeg, g_deg);

    const int TB = 256;
    const int gb_nodes = (NN + TB - 1) / TB;
    const int gb_edges = (ETOT + TB - 1) / TB;
    const int gb_nd    = (NN * DD + TB - 1) / TB;
    const int gb_warp  = (NN * 32 + TB - 1) / TB;   // 1 warp per node
    const int rtiles = (NN + 127) / 128;            // 391

    // CSR build (shared by both GAT layers)
    k_zero_int<<<gb_nodes, TB>>>(pDeg, NN);
    k_deg_count<<<gb_edges, TB>>>(ei);
    k_scan<<<1, 1024>>>();
    k_csr_scatter<<<gb_edges, TB>>>(ei);

    // time-encode + merge
    k_cat<<<gb_nd, TB>>>(nf, ts, freq, phase);
    gemm_mma<<<dim3(1, rtiles), 256>>>(pCAT, merge_W, merge_b, pX,
        NN, 256, DD, nullptr, nullptr, nullptr, nullptr);

    // layer 1: GAT projection (+fused attention dots)
    gemm_mma<<<dim3(1, rtiles), 256>>>(pX, gat1_W, nullptr, pXP,
        NN, DD, DD, gat1_as, gat1_ad, pAS, pAD);
    k_gat_agg<<<gb_warp, TB>>>(pXP, gat1_b, pAGG);
    // layer 1: GRU (+relu) -> H1
    gemm_mma<<<dim3(3, rtiles), 256>>>(pAGG, gru1_Wih, gru1_bih, pGI,
        NN, DD, 3 * DD, nullptr, nullptr, nullptr, nullptr);
    gemm_mma<<<dim3(3, rtiles), 256>>>(x_prev1, gru1_Whh, gru1_bhh, pGH,
        NN, DD, 3 * DD, nullptr, nullptr, nullptr, nullptr);
    k_gru<<<gb_nd, TB>>>(pGI, pGH, x_prev1, nullptr, H1, 1);

    // layer 2: GAT on H1 (+fused attention dots)
    gemm_mma<<<dim3(1, rtiles), 256>>>(H1, gat2_W, nullptr, pXP,
        NN, DD, DD, gat2_as, gat2_ad, pAS, pAD);
    k_gat_agg<<<gb_warp, TB>>>(pXP, gat2_b, pAGG);
    // layer 2: GRU + skip -> H2 (pre-BN)
    gemm_mma<<<dim3(3, rtiles), 256>>>(pAGG, gru2_Wih, gru2_bih, pGI,
        NN, DD, 3 * DD, nullptr, nullptr, nullptr, nullptr);
    gemm_mma<<<dim3(3, rtiles), 256>>>(x_prev2, gru2_Whh, gru2_bhh, pGH,
        NN, DD, 3 * DD, nullptr, nullptr, nullptr, nullptr);
    gemm_mma<<<dim3(1, rtiles), 256>>>(pX, skip_W, skip_b, pXP,
        NN, DD, DD, nullptr, nullptr, nullptr, nullptr);  // skip into XP
    k_gru<<<gb_nd, TB>>>(pGI, pGH, x_prev2, pXP, H2, 0);

    // BatchNorm (training stats, identity affine)
    k_zero_f<<<1, 256>>>(pBN, 256);
    k_bn_reduce<<<rtiles, 128>>>(H2);
    k_bn_norm<<<gb_nd, TB>>>(H2);
}

// round 6
// speedup vs baseline: 1.4474x; 1.2154x over previous
#include <cuda_runtime.h>
#include <cuda_bf16.h>
#include <stdint.h>
#include <math.h>

#define NN   50000
#define EE   640000
#define ETOT (EE + NN)
#define DD   128

typedef __nv_bfloat16 bf16;

// ---------------- scratch (device globals; no allocation allowed) ----------
__device__ __align__(16) bf16  g_CATh[(size_t)NN * 256];
__device__ __align__(16) bf16  g_CATl[(size_t)NN * 256];
__device__ __align__(16) bf16  g_Xh [(size_t)NN * DD];
__device__ __align__(16) bf16  g_Xl [(size_t)NN * DD];
__device__ __align__(16) bf16  g_AGGh[(size_t)NN * DD];
__device__ __align__(16) bf16  g_AGGl[(size_t)NN * DD];
__device__ __align__(16) bf16  g_H1h[(size_t)NN * DD];
__device__ __align__(16) bf16  g_H1l[(size_t)NN * DD];
__device__ __align__(16) bf16  g_P1h[(size_t)NN * DD];
__device__ __align__(16) bf16  g_P1l[(size_t)NN * DD];
__device__ __align__(16) bf16  g_P2h[(size_t)NN * DD];
__device__ __align__(16) bf16  g_P2l[(size_t)NN * DD];
__device__ __align__(16) float g_XP [(size_t)NN * DD];
__device__ __align__(16) float g_GI [(size_t)NN * 3 * DD];
__device__ __align__(16) float g_GH [(size_t)NN * 3 * DD];
#define WT_TOTAL 278528
__device__ __align__(16) bf16  g_WTh[WT_TOTAL];
__device__ __align__(16) bf16  g_WTl[WT_TOTAL];
__device__ float g_ASRC[NN];
__device__ float g_ADST[NN];
__device__ float g_BN[256];
__device__ int   g_deg[NN];
__device__ int   g_off[NN + 1];
__device__ int   g_cur[NN];
__device__ int   g_csr[ETOT];

// WT segment offsets (elems): merge, gat1, wih1, whh1, gat2, wih2, whh2, skip
#define WOFF_MERGE 0
#define WOFF_GAT1  32768
#define WOFF_WIH1  49152
#define WOFF_WHH1  98304
#define WOFF_GAT2  147456
#define WOFF_WIH2  163840
#define WOFF_WHH2  212992
#define WOFF_SKIP  262144

// ---------------- helpers ----------------------------------------------------
__device__ __forceinline__ uint32_t smem_u32(const void* p) {
    uint32_t a;
    asm("{ .reg .u64 t; cvta.to.shared.u64 t, %1; cvt.u32.u64 %0, t; }"
        : "=r"(a) : "l"(p));
    return a;
}
__device__ __forceinline__ void split2(float x0, float x1,
                                       uint32_t& hi, uint32_t& lo) {
    __nv_bfloat162 h = __floats2bfloat162_rn(x0, x1);
    float r0 = x0 - __bfloat162float(h.x);
    float r1 = x1 - __bfloat162float(h.y);
    __nv_bfloat162 l = __floats2bfloat162_rn(r0, r1);
    hi = *reinterpret_cast<uint32_t*>(&h);
    lo = *reinterpret_cast<uint32_t*>(&l);
}
__device__ __forceinline__ void mma_bf16(float c[4], const uint32_t a[4],
                                         uint32_t b0, uint32_t b1) {
    asm volatile(
        "mma.sync.aligned.m16n8k16.row.col.f32.bf16.bf16.f32 "
        "{%0,%1,%2,%3}, {%4,%5,%6,%7}, {%8,%9}, {%0,%1,%2,%3};"
        : "+f"(c[0]), "+f"(c[1]), "+f"(c[2]), "+f"(c[3])
        : "r"(a[0]), "r"(a[1]), "r"(a[2]), "r"(a[3]), "r"(b0), "r"(b1));
}
#define LDSM4(R, addr) \
    asm volatile("ldmatrix.sync.aligned.m8n8.x4.shared.b16 {%0,%1,%2,%3}, [%4];" \
        : "=r"((R)[0]), "=r"((R)[1]), "=r"((R)[2]), "=r"((R)[3]) : "r"(addr))
#define CP16(dst, src, sz) \
    asm volatile("cp.async.cg.shared.global [%0], [%1], 16, %2;" \
        :: "r"(dst), "l"(src), "r"(sz))
#define CP_COMMIT() asm volatile("cp.async.commit_group;")
#define CP_WAIT0()  asm volatile("cp.async.wait_group 0;" ::: "memory")

// ---------------- bf16 split GEMM (pre-split operands, cp.async + ldmatrix) --
// C[r, col0..col0+127] = A[r,:] @ W[:, col0..], A given as (Ah,Al) [nrows][K],
// W given transposed (WTh,WTl) [M][K]. 3-product split compensation.
#define SA      72                 // smem k-stride in bf16 elems (64 + 8 pad)
#define SAB     144                // bytes
#define OFF_AH  0
#define OFF_AL  18432
#define OFF_BH  36864
#define OFF_BL  55296
#define SM_TOT  73728

__global__ __launch_bounds__(256, 2) void gemm_mma(
    const bf16* __restrict__ Ahg, const bf16* __restrict__ Alg,
    const bf16* __restrict__ WTh, const bf16* __restrict__ WTl,
    const float* __restrict__ bias,
    float* __restrict__ C, bf16* __restrict__ Chi, bf16* __restrict__ Clo,
    int nrows, int K, int M,
    const float* __restrict__ attn_s, const float* __restrict__ attn_d,
    float* __restrict__ out_s, float* __restrict__ out_d)
{
    extern __shared__ char dsm[];
    const uint32_t sb  = smem_u32(dsm);
    const uint32_t sAh = sb + OFF_AH, sAl = sb + OFF_AL;
    const uint32_t sBh = sb + OFF_BH, sBl = sb + OFF_BL;

    const int tid = threadIdx.x;
    const int wid = tid >> 5, lane = tid & 31;
    const int g = lane >> 2, tg = lane & 3;
    const int wr = (wid & 3) * 32;
    const int wc = (wid >> 2) * 64;
    const int row0 = blockIdx.y * 128;
    const int col0 = blockIdx.x * 128;

    float c[2][8][4];
#pragma unroll
    for (int mt = 0; mt < 2; mt++)
#pragma unroll
        for (int nt = 0; nt < 8; nt++)
#pragma unroll
            for (int j = 0; j < 4; j++) c[mt][nt][j] = 0.f;

    const uint32_t lrow = lane & 15;             // ldmatrix row within 16
    const uint32_t lkb  = (lane >> 4) * 16;      // ldmatrix k byte offset

    const int nchunks = K >> 6;
    for (int ch = 0; ch < nchunks; ch++) {
        const int k0 = ch << 6;
        if (ch > 0) __syncthreads();             // protect smem reuse
        // ---- stage 64-k chunk of all 4 arrays via cp.async ----
#pragma unroll
        for (int i = 0; i < 4; i++) {
            const int slot = i * 256 + tid;       // 1024 = 128 rows x 8 groups
            const int r = slot >> 3, gk = slot & 7;
            const uint32_t doff = (uint32_t)(r * SAB + gk * 16);
            const size_t asrc = (size_t)(row0 + r) * K + k0 + gk * 8;
            const int oka = (row0 + r < nrows) ? 16 : 0;
            CP16(sAh + doff, Ahg + asrc, oka);
            CP16(sAl + doff, Alg + asrc, oka);
            const size_t bsrc = (size_t)(col0 + r) * K + k0 + gk * 8;
            CP16(sBh + doff, WTh + bsrc, 16);
            CP16(sBl + doff, WTl + bsrc, 16);
        }
        CP_COMMIT();
        CP_WAIT0();
        __syncthreads();

#pragma unroll
        for (int ks = 0; ks < 4; ks++) {
            const uint32_t kb = (uint32_t)(ks * 32) + lkb;   // ks*16 elems *2B
            uint32_t ah[2][4], al[2][4];
#pragma unroll
            for (int mt = 0; mt < 2; mt++) {
                const uint32_t aoff = (uint32_t)((wr + mt * 16 + lrow) * SAB) + kb;
                LDSM4(ah[mt], sAh + aoff);
                LDSM4(al[mt], sAl + aoff);
            }
#pragma unroll
            for (int ntp = 0; ntp < 4; ntp++) {
                const uint32_t boff = (uint32_t)((wc + ntp * 16 + lrow) * SAB) + kb;
                uint32_t bh[4], bl[4];
                LDSM4(bh, sBh + boff);
                LDSM4(bl, sBl + boff);
#pragma unroll
                for (int mt = 0; mt < 2; mt++)
#pragma unroll
                    for (int nb = 0; nb < 2; nb++) {
                        float* cc = c[mt][ntp * 2 + nb];
                        mma_bf16(cc, ah[mt], bh[nb], bh[2 + nb]);
                        mma_bf16(cc, ah[mt], bl[nb], bl[2 + nb]);
                        mma_bf16(cc, al[mt], bh[nb], bh[2 + nb]);
                    }
            }
        }
    }

    // ---- epilogue ----
    float ss[2][2] = {{0.f, 0.f}, {0.f, 0.f}};
    float sd[2][2] = {{0.f, 0.f}, {0.f, 0.f}};
#pragma unroll
    for (int mt = 0; mt < 2; mt++) {
#pragma unroll
        for (int nt = 0; nt < 8; nt++) {
            const int colL = wc + nt * 8 + tg * 2;
            const int col = col0 + colL;
            float b0 = 0.f, b1 = 0.f;
            if (bias) { b0 = bias[col]; b1 = bias[col + 1]; }
            const float v0 = c[mt][nt][0] + b0;
            const float v1 = c[mt][nt][1] + b1;
            const float v2 = c[mt][nt][2] + b0;
            const float v3 = c[mt][nt][3] + b1;
            const int rA = row0 + wr + mt * 16 + g;
            const int rB = rA + 8;
            if (C) {
                if (rA < nrows) *(float2*)&C[(size_t)rA * M + col] = make_float2(v0, v1);
                if (rB < nrows) *(float2*)&C[(size_t)rB * M + col] = make_float2(v2, v3);
            }
            if (Chi) {
                uint32_t h, l;
                if (rA < nrows) {
                    split2(v0, v1, h, l);
                    *(uint32_t*)&Chi[(size_t)rA * M + col] = h;
                    *(uint32_t*)&Clo[(size_t)rA * M + col] = l;
                }
                if (rB < nrows) {
                    split2(v2, v3, h, l);
                    *(uint32_t*)&Chi[(size_t)rB * M + col] = h;
                    *(uint32_t*)&Clo[(size_t)rB * M + col] = l;
                }
            }
            if (out_s) {
                const float s0 = attn_s[colL], s1 = attn_s[colL + 1];
                const float d0 = attn_d[colL], d1 = attn_d[colL + 1];
                ss[mt][0] += v0 * s0 + v1 * s1;
                ss[mt][1] += v2 * s0 + v3 * s1;
                sd[mt][0] += v0 * d0 + v1 * d1;
                sd[mt][1] += v2 * d0 + v3 * d1;
            }
        }
    }
    if (out_s) {
        float* red_s = (float*)dsm;            // alias: 2x128 floats
        float* red_d = red_s + 256;
        __syncthreads();                       // smem free for reuse
#pragma unroll
        for (int mt = 0; mt < 2; mt++)
#pragma unroll
            for (int h = 0; h < 2; h++) {
                ss[mt][h] += __shfl_xor_sync(0xffffffffu, ss[mt][h], 1);
                ss[mt][h] += __shfl_xor_sync(0xffffffffu, ss[mt][h], 2);
                sd[mt][h] += __shfl_xor_sync(0xffffffffu, sd[mt][h], 1);
                sd[mt][h] += __shfl_xor_sync(0xffffffffu, sd[mt][h], 2);
            }
        if (tg == 0) {
            const int wcid = wid >> 2;
#pragma unroll
            for (int mt = 0; mt < 2; mt++)
#pragma unroll
                for (int h = 0; h < 2; h++) {
                    const int rl = wr + mt * 16 + h * 8 + g;
                    red_s[wcid * 128 + rl] = ss[mt][h];
                    red_d[wcid * 128 + rl] = sd[mt][h];
                }
        }
        __syncthreads();
        if (tid < 128) {
            const int r = row0 + tid;
            if (r < nrows) {
                out_s[r] = red_s[tid] + red_s[128 + tid];
                out_d[r] = red_d[tid] + red_d[128 + tid];
            }
        }
    }
}

// ---------------- one-shot weight split + transpose -------------------------
__global__ void k_wsplit(const float* w0, const float* w1, const float* w2,
                         const float* w3, const float* w4, const float* w5,
                         const float* w6, const float* w7)
{
    int idx = blockIdx.x * blockDim.x + threadIdx.x;
    if (idx >= WT_TOTAL) return;
    const int offs[9] = {WOFF_MERGE, WOFF_GAT1, WOFF_WIH1, WOFF_WHH1,
                         WOFF_GAT2, WOFF_WIH2, WOFF_WHH2, WOFF_SKIP, WT_TOTAL};
    const int Ks[8] = {256, 128, 128, 128, 128, 128, 128, 128};
    const int Ms[8] = {128, 128, 384, 384, 128, 384, 384, 128};
    const float* ws[8] = {w0, w1, w2, w3, w4, w5, w6, w7};
    int s = 0;
#pragma unroll
    for (int i = 1; i < 8; i++) if (idx >= offs[i]) s = i;
    const int local = idx - offs[s];
    const int K = Ks[s], M = Ms[s];
    const int m = local / K, k = local % K;
    const float x = ws[s][(size_t)k * M + m];
    bf16 h = __float2bfloat16(x);
    bf16 l = __float2bfloat16(x - __bfloat162float(h));
    g_WTh[idx] = h;
    g_WTl[idx] = l;
}

// ---------------- fp32 -> split bf16 ----------------------------------------
__global__ void k_split(const float* __restrict__ src, bf16* __restrict__ dh,
                        bf16* __restrict__ dl, int n)
{
    int i = blockIdx.x * blockDim.x + threadIdx.x;
    if (i < n) {
        float x = src[i];
        bf16 h = __float2bfloat16(x);
        dh[i] = h;
        dl[i] = __float2bfloat16(x - __bfloat162float(h));
    }
}

// ---------------- graph / CSR build -----------------------------------------
__global__ void k_deg_count(const int* __restrict__ ei) {
    int i = blockIdx.x * blockDim.x + threadIdx.x;
    if (i < ETOT) {
        int d = (i < EE) ? ei[EE + i] : (i - EE);
        atomicAdd(&g_deg[d], 1);
    }
}
__global__ void k_scan() {   // 1 block, 1024 threads, warp-shuffle scan
    __shared__ int wsum[32];
    __shared__ int carry;
    const int tid = threadIdx.x, lane = tid & 31, w = tid >> 5;
    if (tid == 0) carry = 0;
    __syncthreads();
    for (int base = 0; base < NN; base += 1024) {
        const int v = base + tid;
        const int x = (v < NN) ? g_deg[v] : 0;
        int s = x;
#pragma unroll
        for (int o = 1; o < 32; o <<= 1) {
            int t = __shfl_up_sync(0xffffffffu, s, o);
            if (lane >= o) s += t;
        }
        if (lane == 31) wsum[w] = s;
        __syncthreads();
        if (w == 0) {
            int ws = wsum[lane];
#pragma unroll
            for (int o = 1; o < 32; o <<= 1) {
                int t = __shfl_up_sync(0xffffffffu, ws, o);
                if (lane >= o) ws += t;
            }
            wsum[lane] = ws;
        }
        __syncthreads();
        const int pre = (w > 0) ? wsum[w - 1] : 0;
        const int excl = carry + pre + s - x;
        const int tot = wsum[31];
        if (v < NN) { g_off[v] = excl; g_cur[v] = excl; }
        __syncthreads();
        if (tid == 0) carry += tot;
        __syncthreads();
    }
    if (tid == 0) g_off[NN] = carry;
}
__global__ void k_csr_scatter(const int* __restrict__ ei) {
    int i = blockIdx.x * blockDim.x + threadIdx.x;
    if (i < ETOT) {
        int s, d;
        if (i < EE) { s = ei[i]; d = ei[EE + i]; }
        else        { s = i - EE; d = i - EE; }
        int slot = atomicAdd(&g_cur[d], 1);
        g_csr[slot] = s;
    }
}

// ---------------- time encode + concat (split bf16 out) ---------------------
__global__ void k_cat(const float* __restrict__ nf, const float* __restrict__ ts,
                      const float* __restrict__ freq, const float* __restrict__ phase)
{
    int idx = blockIdx.x * blockDim.x + threadIdx.x;
    if (idx < NN * DD) {
        int n = idx >> 7, j = idx & 127;
        float a = nf[idx];
        float b = cosf(ts[n] * freq[j] + phase[j]);
        bf16 ah = __float2bfloat16(a);
        bf16 bh = __float2bfloat16(b);
        size_t base = (size_t)n * 256;
        g_CATh[base + j] = ah;
        g_CATl[base + j] = __float2bfloat16(a - __bfloat162float(ah));
        g_CATh[base + 128 + j] = bh;
        g_CATl[base + 128 + j] = __float2bfloat16(b - __bfloat162float(bh));
    }
}

// ---------------- GAT aggregation: warp per dst node, split bf16 out --------
__global__ void k_gat_agg(const float* __restrict__ XP,
                          const float* __restrict__ bias,
                          bf16* __restrict__ oh, bf16* __restrict__ ol)
{
    int v = (blockIdx.x * blockDim.x + threadIdx.x) >> 5;
    int lane = threadIdx.x & 31;
    if (v >= NN) return;
    const int beg = g_off[v], end = g_off[v + 1];
    const float adv = g_ADST[v];

    float m = -1e30f;
    for (int i = beg + lane; i < end; i += 32) {
        float e = g_ASRC[g_csr[i]] + adv;
        e = (e > 0.f) ? e : 0.2f * e;
        m = fmaxf(m, e);
    }
#pragma unroll
    for (int o = 16; o; o >>= 1) m = fmaxf(m, __shfl_xor_sync(0xffffffffu, m, o));

    float ssum = 0.f;
    float4 acc = make_float4(0.f, 0.f, 0.f, 0.f);
    for (int i = beg; i < end; i++) {
        const int s = g_csr[i];
        float e = g_ASRC[s] + adv;
        e = (e > 0.f) ? e : 0.2f * e;
        const float w = expf(e - m);
        ssum += w;
        const float4 xv = *(const float4*)&XP[(size_t)s * DD + lane * 4];
        acc.x += w * xv.x; acc.y += w * xv.y;
        acc.z += w * xv.z; acc.w += w * xv.w;
    }
    const float inv = 1.f / (ssum + 1e-16f);
    const float4 b4 = *(const float4*)&bias[lane * 4];
    const float o0 = acc.x * inv + b4.x, o1 = acc.y * inv + b4.y;
    const float o2 = acc.z * inv + b4.z, o3 = acc.w * inv + b4.w;
    uint32_t h01, l01, h23, l23;
    split2(o0, o1, h01, l01);
    split2(o2, o3, h23, l23);
    const size_t base = (size_t)v * DD + lane * 4;
    *(uint32_t*)&oh[base]     = h01;
    *(uint32_t*)&oh[base + 2] = h23;
    *(uint32_t*)&ol[base]     = l01;
    *(uint32_t*)&ol[base + 2] = l23;
}

// ---------------- GRU gates (+relu/skip, optional split out) ----------------
__global__ void k_gru(const float* __restrict__ GI, const float* __restrict__ GH,
                      const float* __restrict__ h, const float* __restrict__ skip,
                      float* __restrict__ out, bf16* __restrict__ oh,
                      bf16* __restrict__ ol, int do_relu)
{
    int idx = blockIdx.x * blockDim.x + threadIdx.x;
    if (idx >= NN * DD) return;
    int n = idx >> 7, j = idx & 127;
    size_t base = (size_t)n * 3 * DD;
    float ir = GI[base + j],        hr = GH[base + j];
    float iz = GI[base + DD + j],   hz = GH[base + DD + j];
    float in_ = GI[base + 2 * DD + j], hn = GH[base + 2 * DD + j];
    float r = 1.f / (1.f + expf(-(ir + hr)));
    float z = 1.f / (1.f + expf(-(iz + hz)));
    float nn = tanhf(in_ + r * hn);
    float hv = h[idx];
    float o = (1.f - z) * nn + z * hv;
    if (skip) o += skip[idx];
    if (do_relu) o = fmaxf(o, 0.f);
    out[idx] = o;
    if (oh) {
        bf16 hh = __float2bfloat16(o);
        oh[idx] = hh;
        ol[idx] = __float2bfloat16(o - __bfloat162float(hh));
    }
}

// ---------------- BatchNorm over rows ----------------------------------------
__global__ void k_bn_reduce(const float* __restrict__ H2) {
    int c = threadIdx.x;
    int r0 = blockIdx.x * 128;
    int rend = min(r0 + 128, NN);
    float s = 0.f, s2 = 0.f;
    for (int r = r0; r < rend; r++) {
        float v = H2[(size_t)r * DD + c];
        s += v; s2 += v * v;
    }
    atomicAdd(&g_BN[c], s);
    atomicAdd(&g_BN[128 + c], s2);
}
__global__ void k_bn_norm(float* __restrict__ H2) {
    int idx = blockIdx.x * blockDim.x + threadIdx.x;
    if (idx >= NN * DD) return;
    int j = idx & 127;
    float mu = g_BN[j] * (1.f / NN);
    float var = g_BN[128 + j] * (1.f / NN) - mu * mu;
    H2[idx] = (H2[idx] - mu) * rsqrtf(var + 1e-5f);
}

// ---------------- launch ------------------------------------------------------
extern "C" void kernel_launch(void* const* d_in, const int* in_sizes, int n_in,
                              void* d_out, int out_size)
{
    const float* nf       = (const float*)d_in[0];
    const int*   ei       = (const int*)  d_in[1];
    const float* x_prev1  = (const float*)d_in[2];
    const float* x_prev2  = (const float*)d_in[3];
    const float* ts       = (const float*)d_in[4];
    const float* freq     = (const float*)d_in[5];
    const float* phase    = (const float*)d_in[6];
    const float* merge_W  = (const float*)d_in[7];
    const float* merge_b  = (const float*)d_in[8];
    const float* gat1_W   = (const float*)d_in[9];
    const float* gat1_as  = (const float*)d_in[10];
    const float* gat1_ad  = (const float*)d_in[11];
    const float* gat1_b   = (const float*)d_in[12];
    const float* gru1_Wih = (const float*)d_in[13];
    const float* gru1_Whh = (const float*)d_in[14];
    const float* gru1_bih = (const float*)d_in[15];
    const float* gru1_bhh = (const float*)d_in[16];
    const float* gat2_W   = (const float*)d_in[17];
    const float* gat2_as  = (const float*)d_in[18];
    const float* gat2_ad  = (const float*)d_in[19];
    const float* gat2_b   = (const float*)d_in[20];
    const float* gru2_Wih = (const float*)d_in[21];
    const float* gru2_Whh = (const float*)d_in[22];
    const float* gru2_bih = (const float*)d_in[23];
    const float* gru2_bhh = (const float*)d_in[24];
    const float* skip_W   = (const float*)d_in[25];
    const float* skip_b   = (const float*)d_in[26];

    float* H1 = (float*)d_out;
    float* H2 = H1 + (size_t)NN * DD;

    float *pXP, *pGI, *pGH, *pBN, *pAS, *pAD;
    bf16 *pCATh, *pCATl, *pXh, *pXl, *pAGGh, *pAGGl, *pH1h, *pH1l;
    bf16 *pP1h, *pP1l, *pP2h, *pP2l, *pWTh, *pWTl;
    int *pDeg;
    cudaGetSymbolAddress((void**)&pXP,   g_XP);
    cudaGetSymbolAddress((void**)&pGI,   g_GI);
    cudaGetSymbolAddress((void**)&pGH,   g_GH);
    cudaGetSymbolAddress((void**)&pBN,   g_BN);
    cudaGetSymbolAddress((void**)&pAS,   g_ASRC);
    cudaGetSymbolAddress((void**)&pAD,   g_ADST);
    cudaGetSymbolAddress((void**)&pCATh, g_CATh);
    cudaGetSymbolAddress((void**)&pCATl, g_CATl);
    cudaGetSymbolAddress((void**)&pXh,   g_Xh);
    cudaGetSymbolAddress((void**)&pXl,   g_Xl);
    cudaGetSymbolAddress((void**)&pAGGh, g_AGGh);
    cudaGetSymbolAddress((void**)&pAGGl, g_AGGl);
    cudaGetSymbolAddress((void**)&pH1h,  g_H1h);
    cudaGetSymbolAddress((void**)&pH1l,  g_H1l);
    cudaGetSymbolAddress((void**)&pP1h,  g_P1h);
    cudaGetSymbolAddress((void**)&pP1l,  g_P1l);
    cudaGetSymbolAddress((void**)&pP2h,  g_P2h);
    cudaGetSymbolAddress((void**)&pP2l,  g_P2l);
    cudaGetSymbolAddress((void**)&pWTh,  g_WTh);
    cudaGetSymbolAddress((void**)&pWTl,  g_WTl);
    cudaGetSymbolAddress((void**)&pDeg,  g_deg);

    cudaFuncSetAttribute(gemm_mma, cudaFuncAttributeMaxDynamicSharedMemorySize,
                         SM_TOT);

    const int TB = 256;
    const int gb_edges = (ETOT + TB - 1) / TB;
    const int gb_nd    = (NN * DD + TB - 1) / TB;
    const int gb_warp  = (NN * 32 + TB - 1) / TB;
    const int rtiles   = (NN + 127) / 128;

    cudaMemsetAsync(pDeg, 0, NN * sizeof(int));
    cudaMemsetAsync(pBN, 0, 256 * sizeof(float));

    // 1: time-encode + concat (split)
    k_cat<<<gb_nd, TB>>>(nf, ts, freq, phase);
    // 2: all weight splits+transposes
    k_wsplit<<<(WT_TOTAL + TB - 1) / TB, TB>>>(merge_W, gat1_W, gru1_Wih,
        gru1_Whh, gat2_W, gru2_Wih, gru2_Whh, skip_W);
    // 3: x_prev1 split
    k_split<<<gb_nd, TB>>>(x_prev1, pP1h, pP1l, NN * DD);
    // 4: merge GEMM -> X (split only)   [ncu capture slot]
    gemm_mma<<<dim3(1, rtiles), 256, SM_TOT>>>(pCATh, pCATl,
        pWTh + WOFF_MERGE, pWTl + WOFF_MERGE, merge_b,
        nullptr, pXh, pXl, NN, 256, DD, nullptr, nullptr, nullptr, nullptr);
    // CSR build
    k_deg_count<<<gb_edges, TB>>>(ei);
    k_scan<<<1, 1024>>>();
    k_csr_scatter<<<gb_edges, TB>>>(ei);
    // x_prev2 split
    k_split<<<gb_nd, TB>>>(x_prev2, pP2h, pP2l, NN * DD);

    // layer 1: GAT projection (+fused attention dots)
    gemm_mma<<<dim3(1, rtiles), 256, SM_TOT>>>(pXh, pXl,
        pWTh + WOFF_GAT1, pWTl + WOFF_GAT1, nullptr,
        pXP, nullptr, nullptr, NN, DD, DD, gat1_as, gat1_ad, pAS, pAD);
    k_gat_agg<<<gb_warp, TB>>>(pXP, gat1_b, pAGGh, pAGGl);
    gemm_mma<<<dim3(3, rtiles), 256, SM_TOT>>>(pAGGh, pAGGl,
        pWTh + WOFF_WIH1, pWTl + WOFF_WIH1, gru1_bih,
        pGI, nullptr, nullptr, NN, DD, 3 * DD, nullptr, nullptr, nullptr, nullptr);
    gemm_mma<<<dim3(3, rtiles), 256, SM_TOT>>>(pP1h, pP1l,
        pWTh + WOFF_WHH1, pWTl + WOFF_WHH1, gru1_bhh,
        pGH, nullptr, nullptr, NN, DD, 3 * DD, nullptr, nullptr, nullptr, nullptr);
    k_gru<<<gb_nd, TB>>>(pGI, pGH, x_prev1, nullptr, H1, pH1h, pH1l, 1);

    // layer 2
    gemm_mma<<<dim3(1, rtiles), 256, SM_TOT>>>(pH1h, pH1l,
        pWTh + WOFF_GAT2, pWTl + WOFF_GAT2, nullptr,
        pXP, nullptr, nullptr, NN, DD, DD, gat2_as, gat2_ad, pAS, pAD);
    k_gat_agg<<<gb_warp, TB>>>(pXP, gat2_b, pAGGh, pAGGl);
    gemm_mma<<<dim3(3, rtiles), 256, SM_TOT>>>(pAGGh, pAGGl,
        pWTh + WOFF_WIH2, pWTl + WOFF_WIH2, gru2_bih,
        pGI, nullptr, nullptr, NN, DD, 3 * DD, nullptr, nullptr, nullptr, nullptr);
    gemm_mma<<<dim3(3, rtiles), 256, SM_TOT>>>(pP2h, pP2l,
        pWTh + WOFF_WHH2, pWTl + WOFF_WHH2, gru2_bhh,
        pGH, nullptr, nullptr, NN, DD, 3 * DD, nullptr, nullptr, nullptr, nullptr);
    gemm_mma<<<dim3(1, rtiles), 256, SM_TOT>>>(pXh, pXl,
        pWTh + WOFF_SKIP, pWTl + WOFF_SKIP, skip_b,
        pXP, nullptr, nullptr, NN, DD, DD, nullptr, nullptr, nullptr, nullptr);
    k_gru<<<gb_nd, TB>>>(pGI, pGH, x_prev2, pXP, H2, nullptr, nullptr, 0);

    // BatchNorm
    k_bn_reduce<<<rtiles, 128>>>(H2);
    k_bn_norm<<<gb_nd, TB>>>(H2);
}